// round 3
// baseline (speedup 1.0000x reference)
#include <cuda_runtime.h>

#define NS    8192
#define NHALF 4096
#define D     256

// Device-global scratch (no allocations allowed in kernel_launch).
__device__ double g_acc;
__device__ float  g_colsum[D];
__device__ float  g_sq[NS];
__device__ float  g_C;   // log2(e) / (16*b)

__device__ __forceinline__ float ex2f_fast(float x) {
    float y;
    asm("ex2.approx.f32 %0, %1;" : "=f"(y) : "f"(x));
    return y;
}

__device__ __forceinline__ const float* row_ptr(const float* __restrict__ s,
                                                const float* __restrict__ t, int i) {
    return (i < NHALF) ? (s + (size_t)i * D) : (t + (size_t)(i - NHALF) * D);
}

// ---------------------------------------------------------------------------
__global__ void k_zero() {
    int t = threadIdx.x;
    if (t < D) g_colsum[t] = 0.0f;
    if (t == 0) g_acc = 0.0;
}

// One warp per row: squared L2 norm of each of the 8192 rows.
__global__ void k_rowsq(const float* __restrict__ s, const float* __restrict__ t) {
    int warp = threadIdx.x >> 5, lane = threadIdx.x & 31;
    int row = blockIdx.x * 8 + warp;
    const float4* p = (const float4*)row_ptr(s, t, row);
    float4 a = p[lane];
    float4 b = p[lane + 32];
    float v = a.x * a.x + a.y * a.y + a.z * a.z + a.w * a.w
            + b.x * b.x + b.y * b.y + b.z * b.z + b.w * b.w;
    #pragma unroll
    for (int o = 16; o; o >>= 1) v += __shfl_down_sync(0xffffffffu, v, o);
    if (lane == 0) g_sq[row] = v;
}

// Column sums (for ||sum_i x_i||^2 in the closed-form bandwidth).
__global__ void k_colsum(const float* __restrict__ s, const float* __restrict__ t) {
    int d  = threadIdx.x;
    int r0 = blockIdx.x * 128;
    float acc = 0.0f;
    for (int r = r0; r < r0 + 128; ++r) acc += row_ptr(s, t, r)[d];
    atomicAdd(&g_colsum[d], acc);
}

// bandwidth: sum(l2) = 2*ns*sum(sq) - 2*||colsum||^2 ; b = bandwidth/4 ;
// g_C = log2(e)/(16*b)  so  u = exp2(-l2*g_C) = exp(-l2/(16b)).
__global__ void k_bw() {
    __shared__ float red[256];
    int t = threadIdx.x;
    float ss = 0.0f;
    for (int k = t; k < NS; k += 256) ss += g_sq[k];
    red[t] = ss; __syncthreads();
    for (int o = 128; o; o >>= 1) { if (t < o) red[t] += red[t + o]; __syncthreads(); }
    float sumsq = red[0]; __syncthreads();
    float c = g_colsum[t];
    red[t] = c * c; __syncthreads();
    for (int o = 128; o; o >>= 1) { if (t < o) red[t] += red[t + o]; __syncthreads(); }
    if (t == 0) {
        double suml2 = 2.0 * (double)NS * (double)sumsq - 2.0 * (double)red[0];
        double bw = suml2 / ((double)NS * (double)NS - (double)NS);
        double b = bw / 4.0;  // KERNEL_MUL^(KERNEL_NUM//2) = 2^2
        g_C = (float)(1.4426950408889634 / (16.0 * b));
    }
}

// ---------------------------------------------------------------------------
// Fused Gram + multi-bandwidth Gaussian-kernel epilogue, upper-triangle tiles.
// 64x64 output tile / block, 256 threads, each thread a 4x4 micro-tile.
__global__ __launch_bounds__(256) void k_mmd(const float* __restrict__ s,
                                             const float* __restrict__ t) {
    int ib = blockIdx.x, jb = blockIdx.y;
    if (jb < ib) return;  // symmetry: J >= I only

    __shared__ float As[32][68];
    __shared__ float Bs[32][68];
    __shared__ float red[256];

    int tid = threadIdx.x;
    int tx = tid & 15, ty = tid >> 4;
    int rI = ib * 64, rJ = jb * 64;

    float acc[4][4] = {};

    for (int k0 = 0; k0 < D; k0 += 32) {
        #pragma unroll
        for (int l = 0; l < 2; ++l) {
            int idx = tid + l * 256;      // 0..511 -> (row, 4-col group)
            int r = idx >> 3, c4 = idx & 7;
            const float* pa = row_ptr(s, t, rI + r) + k0 + c4 * 4;
            float4 va = *(const float4*)pa;
            As[c4 * 4 + 0][r] = va.x; As[c4 * 4 + 1][r] = va.y;
            As[c4 * 4 + 2][r] = va.z; As[c4 * 4 + 3][r] = va.w;
            const float* pb = row_ptr(s, t, rJ + r) + k0 + c4 * 4;
            float4 vb = *(const float4*)pb;
            Bs[c4 * 4 + 0][r] = vb.x; Bs[c4 * 4 + 1][r] = vb.y;
            Bs[c4 * 4 + 2][r] = vb.z; Bs[c4 * 4 + 3][r] = vb.w;
        }
        __syncthreads();

        #pragma unroll 8
        for (int k = 0; k < 32; ++k) {
            float4 a = *(const float4*)&As[k][ty * 4];
            float4 b = *(const float4*)&Bs[k][tx * 4];
            float av[4] = {a.x, a.y, a.z, a.w};
            float bv[4] = {b.x, b.y, b.z, b.w};
            #pragma unroll
            for (int i = 0; i < 4; ++i)
                #pragma unroll
                for (int j = 0; j < 4; ++j)
                    acc[i][j] = fmaf(av[i], bv[j], acc[i][j]);
        }
        __syncthreads();
    }

    // Epilogue: l2 -> 5-bandwidth kernel sum via one EX2 + 4 squarings.
    float C = g_C;
    float sqi[4], sqj[4];
    #pragma unroll
    for (int i = 0; i < 4; ++i) {
        sqi[i] = g_sq[rI + ty * 4 + i];
        sqj[i] = g_sq[rJ + tx * 4 + i];
    }
    // tiles are sign-pure (64 divides 4096)
    float sgn = ((rI < NHALF) == (rJ < NHALF)) ? 1.0f : -1.0f;
    float fac = (ib == jb) ? sgn : 2.0f * sgn;

    float partial = 0.0f;
    #pragma unroll
    for (int i = 0; i < 4; ++i)
        #pragma unroll
        for (int j = 0; j < 4; ++j) {
            float l2 = sqi[i] + sqj[j] - 2.0f * acc[i][j];
            float u  = ex2f_fast(-l2 * C);   // exp(-l2/(16b))
            float u2 = u * u, u4 = u2 * u2, u8 = u4 * u4, u16 = u8 * u8;
            partial += (u + u2) + (u4 + u8) + u16;
        }
    partial *= fac;

    red[tid] = partial;
    __syncthreads();
    for (int o = 128; o >= 32; o >>= 1) {
        if (tid < o) red[tid] += red[tid + o];
        __syncthreads();
    }
    if (tid < 32) {
        float v = red[tid];
        #pragma unroll
        for (int o = 16; o; o >>= 1) v += __shfl_down_sync(0xffffffffu, v, o);
        if (tid == 0) atomicAdd(&g_acc, (double)v);
    }
}

__global__ void k_fin(float* out) {
    out[0] = (float)(g_acc / ((double)NHALF * (double)NHALF));
}

// ---------------------------------------------------------------------------
extern "C" void kernel_launch(void* const* d_in, const int* in_sizes, int n_in,
                              void* d_out, int out_size) {
    const float* s = (const float*)d_in[0];
    const float* t = (const float*)d_in[1];
    float* out = (float*)d_out;

    k_zero<<<1, 256>>>();
    k_rowsq<<<1024, 256>>>(s, t);
    k_colsum<<<64, 256>>>(s, t);
    k_bw<<<1, 256>>>();
    dim3 g(128, 128);
    k_mmd<<<g, 256>>>(s, t);
    k_fin<<<1, 1>>>(out);
}

// round 5
// speedup vs baseline: 3.3669x; 3.3669x over previous
#include <cuda_runtime.h>
#include <cuda_bf16.h>
#include <cstdint>

#define NS    8192
#define NHALF 4096
#define D     256
#define KTOT  512          // bf16-split K = 2*D
#define TS    128          // output tile (M=N)
#define KC    64           // K elems per smem stage (64 bf16 = 128B rows)
#define NSTAGE (KTOT / KC) // 8

// ---- device-global scratch (no allocs allowed) ------------------------------
__device__ double g_acc;
__device__ float  g_colsum[D];
__device__ float  g_sq[NS];
__device__ float  g_C;                       // log2(e) / (16*b)
__device__ __align__(16) __nv_bfloat16 g_Y[(size_t)NS * KTOT];   // 8 MB

// ---- helpers ----------------------------------------------------------------
__device__ __forceinline__ float ex2f_fast(float x) {
    float y; asm("ex2.approx.f32 %0, %1;" : "=f"(y) : "f"(x)); return y;
}
__device__ __forceinline__ uint32_t smem_u32(const void* p) {
    uint32_t a;
    asm("{ .reg .u64 t; cvta.to.shared.u64 t, %1; cvt.u32.u64 %0, t; }" : "=r"(a) : "l"(p));
    return a;
}
__device__ __forceinline__ void cp16(uint32_t dst, const void* src) {
    asm volatile("cp.async.cg.shared.global [%0], [%1], 16;" :: "r"(dst), "l"(src));
}
#define CP_COMMIT() asm volatile("cp.async.commit_group;" ::: "memory")
#define CP_WAIT(n)  asm volatile("cp.async.wait_group %0;" :: "n"(n) : "memory")

__device__ __forceinline__ void ldm4(uint32_t* r, uint32_t a) {
    asm volatile("ldmatrix.sync.aligned.m8n8.x4.shared.b16 {%0,%1,%2,%3}, [%4];"
        : "=r"(r[0]), "=r"(r[1]), "=r"(r[2]), "=r"(r[3]) : "r"(a));
}
__device__ __forceinline__ void mma16816(float* c, const uint32_t* a, const uint32_t* b) {
    asm volatile("mma.sync.aligned.m16n8k16.row.col.f32.bf16.bf16.f32 "
        "{%0,%1,%2,%3}, {%4,%5,%6,%7}, {%8,%9}, {%0,%1,%2,%3};"
        : "+f"(c[0]), "+f"(c[1]), "+f"(c[2]), "+f"(c[3])
        : "r"(a[0]), "r"(a[1]), "r"(a[2]), "r"(a[3]), "r"(b[0]), "r"(b[1]));
}

// SW128-style XOR swizzle for tiles with 128-byte rows.
__device__ __forceinline__ uint32_t swz(uint32_t off) {
    return off ^ ((off >> 3) & 0x70);
}

__device__ __forceinline__ const float* row_ptr(const float* __restrict__ s,
                                                const float* __restrict__ t, int i) {
    return (i < NHALF) ? (s + (size_t)i * D) : (t + (size_t)(i - NHALF) * D);
}

// ---------------------------------------------------------------------------
__global__ void k_zero() {
    int t = threadIdx.x;
    if (t < D) g_colsum[t] = 0.0f;
    if (t == 0) g_acc = 0.0;
}

// One warp per row: squared L2 norm of each of the 8192 rows.
__global__ void k_rowsq(const float* __restrict__ s, const float* __restrict__ t) {
    int warp = threadIdx.x >> 5, lane = threadIdx.x & 31;
    int row = blockIdx.x * 8 + warp;
    const float4* p = (const float4*)row_ptr(s, t, row);
    float4 a = p[lane];
    float4 b = p[lane + 32];
    float v = a.x * a.x + a.y * a.y + a.z * a.z + a.w * a.w
            + b.x * b.x + b.y * b.y + b.z * b.z + b.w * b.w;
    #pragma unroll
    for (int o = 16; o; o >>= 1) v += __shfl_down_sync(0xffffffffu, v, o);
    if (lane == 0) g_sq[row] = v;
}

__global__ void k_colsum(const float* __restrict__ s, const float* __restrict__ t) {
    int d  = threadIdx.x;
    int r0 = blockIdx.x * 128;
    float acc = 0.0f;
    for (int r = r0; r < r0 + 128; ++r) acc += row_ptr(s, t, r)[d];
    atomicAdd(&g_colsum[d], acc);
}

// bandwidth: sum(l2) = 2*ns*sum(sq) - 2*||colsum||^2 ; b = bw/4 ;
// g_C = log2(e)/(16*b)  so  u = exp2(-l2*g_C) = exp(-l2/(16b)).
__global__ void k_bw() {
    __shared__ float red[256];
    int t = threadIdx.x;
    float ss = 0.0f;
    for (int k = t; k < NS; k += 256) ss += g_sq[k];
    red[t] = ss; __syncthreads();
    for (int o = 128; o; o >>= 1) { if (t < o) red[t] += red[t + o]; __syncthreads(); }
    float sumsq = red[0]; __syncthreads();
    float c = g_colsum[t];
    red[t] = c * c; __syncthreads();
    for (int o = 128; o; o >>= 1) { if (t < o) red[t] += red[t + o]; __syncthreads(); }
    if (t == 0) {
        double suml2 = 2.0 * (double)NS * (double)sumsq - 2.0 * (double)red[0];
        double bw = suml2 / ((double)NS * (double)NS - (double)NS);
        double b = bw / 4.0;   // KERNEL_MUL^(KERNEL_NUM//2) = 2^2
        g_C = (float)(1.4426950408889634 / (16.0 * b));
    }
}

// Split fp32 rows into bf16 (hi | lo): Y[r, 0:256]=hi, Y[r, 256:512]=lo.
__global__ void k_split(const float* __restrict__ s, const float* __restrict__ t) {
    int idx = blockIdx.x * 256 + threadIdx.x;   // one float4 (4 elems) per thread
    int row = idx >> 6;                          // 64 float4 per row
    int c4  = idx & 63;
    float4 v = ((const float4*)row_ptr(s, t, row))[c4];
    __nv_bfloat16 h0 = __float2bfloat16(v.x), h1 = __float2bfloat16(v.y),
                  h2 = __float2bfloat16(v.z), h3 = __float2bfloat16(v.w);
    __nv_bfloat16 l0 = __float2bfloat16(v.x - __bfloat162float(h0));
    __nv_bfloat16 l1 = __float2bfloat16(v.y - __bfloat162float(h1));
    __nv_bfloat16 l2 = __float2bfloat16(v.z - __bfloat162float(h2));
    __nv_bfloat16 l3 = __float2bfloat16(v.w - __bfloat162float(h3));
    __nv_bfloat162* hi = (__nv_bfloat162*)(g_Y + (size_t)row * KTOT + c4 * 4);
    __nv_bfloat162* lo = (__nv_bfloat162*)(g_Y + (size_t)row * KTOT + 256 + c4 * 4);
    hi[0] = __nv_bfloat162(h0, h1); hi[1] = __nv_bfloat162(h2, h3);
    lo[0] = __nv_bfloat162(l0, l1); lo[1] = __nv_bfloat162(l2, l3);
}

// ---------------------------------------------------------------------------
// Warp-MMA fused Gram + multi-bandwidth Gaussian epilogue.
// Grid 64x64 upper triangle. 128x128 tile, 8 warps * (64x32 warp tile).
// K=512 in 8 stages of 64, cp.async double-buffered, SW128 swizzle + ldmatrix.
// Dynamic smem: 2 bufs * (A 16KB + B 16KB) = 64KB.
#define STAGE_BYTES 32768                    // A(16KB) + B(16KB)
#define SMEM_TOTAL  (2 * STAGE_BYTES)

__global__ __launch_bounds__(256) void k_mmd() {
    int ib = blockIdx.x, jb = blockIdx.y;
    if (jb < ib) return;

    extern __shared__ char sm[];
    __shared__ float s_sqi[128], s_sqj[128], s_red[256];
    uint32_t sbase = smem_u32(sm);

    int tid  = threadIdx.x;
    int warp = tid >> 5, lane = tid & 31;
    int wm = warp >> 2, wn = warp & 3;        // warp tile: rows wm*64, cols wn*32
    int rI = ib * TS, rJ = jb * TS;

    if (tid < 128) s_sqi[tid] = g_sq[rI + tid];
    else           s_sqj[tid - 128] = g_sq[rJ + tid - 128];

    const __nv_bfloat16* YA = g_Y + (size_t)rI * KTOT;
    const __nv_bfloat16* YB = g_Y + (size_t)rJ * KTOT;

    // per-thread copy coordinates: 4 chunks of 16B for A and for B per stage
    // chunk = tid + t*256 ; row = chunk>>3 ; 16B-col = chunk&7
    auto issue_stage = [&](int st, int buf) {
        int k0 = st * KC;
        uint32_t base = sbase + buf * STAGE_BYTES;
        #pragma unroll
        for (int t = 0; t < 4; ++t) {
            int chunk = tid + t * 256;
            int r = chunk >> 3, c16 = chunk & 7;
            uint32_t d = swz((uint32_t)(r * 128 + c16 * 16));
            cp16(base + d,         YA + (size_t)r * KTOT + k0 + c16 * 8);
            cp16(base + 16384 + d, YB + (size_t)r * KTOT + k0 + c16 * 8);
        }
        CP_COMMIT();
    };

    float acc[4][4][4] = {};

    issue_stage(0, 0);

    for (int st = 0; st < NSTAGE; ++st) {
        if (st + 1 < NSTAGE) { issue_stage(st + 1, (st + 1) & 1); CP_WAIT(1); }
        else                 { CP_WAIT(0); }
        __syncthreads();

        uint32_t Ab = sbase + (st & 1) * STAGE_BYTES;
        uint32_t Bb = Ab + 16384;

        #pragma unroll
        for (int kk = 0; kk < KC; kk += 16) {
            int kb = (kk + ((lane >> 4) * 8)) * 2;     // byte col within 128B row
            uint32_t afr[4][4], bfr[4][2];
            #pragma unroll
            for (int i = 0; i < 4; ++i) {
                int row = wm * 64 + i * 16 + (lane & 15);
                ldm4(afr[i], Ab + swz((uint32_t)(row * 128 + kb)));
            }
            #pragma unroll
            for (int j2 = 0; j2 < 2; ++j2) {
                uint32_t q[4];
                int row = wn * 32 + j2 * 16 + (lane & 15);
                ldm4(q, Bb + swz((uint32_t)(row * 128 + kb)));
                bfr[j2 * 2 + 0][0] = q[0]; bfr[j2 * 2 + 0][1] = q[2];
                bfr[j2 * 2 + 1][0] = q[1]; bfr[j2 * 2 + 1][1] = q[3];
            }
            #pragma unroll
            for (int i = 0; i < 4; ++i)
                #pragma unroll
                for (int j = 0; j < 4; ++j)
                    mma16816(acc[i][j], afr[i], bfr[j]);
        }
        __syncthreads();
    }

    // ---- fused epilogue on C fragments ----
    float C = g_C;
    float partial = 0.0f;
    #pragma unroll
    for (int i = 0; i < 4; ++i) {
        int r_lo = wm * 64 + i * 16 + (lane >> 2);
        float sq_lo = s_sqi[r_lo], sq_hi = s_sqi[r_lo + 8];
        #pragma unroll
        for (int j = 0; j < 4; ++j) {
            int c_lo = wn * 32 + j * 8 + (lane & 3) * 2;
            float sc0 = s_sqj[c_lo], sc1 = s_sqj[c_lo + 1];
            float l2a = sq_lo + sc0 - 2.0f * acc[i][j][0];
            float l2b = sq_lo + sc1 - 2.0f * acc[i][j][1];
            float l2c = sq_hi + sc0 - 2.0f * acc[i][j][2];
            float l2d = sq_hi + sc1 - 2.0f * acc[i][j][3];
            float ua = ex2f_fast(-l2a * C), ub = ex2f_fast(-l2b * C);
            float uc = ex2f_fast(-l2c * C), ud = ex2f_fast(-l2d * C);
            float t, s4 = 0.0f;
            t = ua; s4 += t; t *= t; s4 += t; t *= t; s4 += t; t *= t; s4 += t; t *= t; s4 += t;
            t = ub; s4 += t; t *= t; s4 += t; t *= t; s4 += t; t *= t; s4 += t; t *= t; s4 += t;
            t = uc; s4 += t; t *= t; s4 += t; t *= t; s4 += t; t *= t; s4 += t; t *= t; s4 += t;
            t = ud; s4 += t; t *= t; s4 += t; t *= t; s4 += t; t *= t; s4 += t; t *= t; s4 += t;
            partial += s4;
        }
    }
    float sgn = ((ib < 32) == (jb < 32)) ? 1.0f : -1.0f;
    partial *= (ib == jb) ? sgn : 2.0f * sgn;

    s_red[tid] = partial;
    __syncthreads();
    for (int o = 128; o >= 32; o >>= 1) {
        if (tid < o) s_red[tid] += s_red[tid + o];
        __syncthreads();
    }
    if (tid < 32) {
        float v = s_red[tid];
        #pragma unroll
        for (int o = 16; o; o >>= 1) v += __shfl_down_sync(0xffffffffu, v, o);
        if (tid == 0) atomicAdd(&g_acc, (double)v);
    }
}

__global__ void k_fin(float* out) {
    out[0] = (float)(g_acc / ((double)NHALF * (double)NHALF));
}

// ---------------------------------------------------------------------------
extern "C" void kernel_launch(void* const* d_in, const int* in_sizes, int n_in,
                              void* d_out, int out_size) {
    const float* s = (const float*)d_in[0];
    const float* t = (const float*)d_in[1];
    float* out = (float*)d_out;

    cudaFuncSetAttribute(k_mmd, cudaFuncAttributeMaxDynamicSharedMemorySize, SMEM_TOTAL);

    k_zero<<<1, 256>>>();
    k_rowsq<<<1024, 256>>>(s, t);
    k_colsum<<<64, 256>>>(s, t);
    k_split<<<2048, 256>>>(s, t);
    k_bw<<<1, 256>>>();
    dim3 g(64, 64);
    k_mmd<<<g, 256, SMEM_TOTAL>>>();
    k_fin<<<1, 1>>>(out);
}

// round 6
// speedup vs baseline: 5.6126x; 1.6670x over previous
#include <cuda_runtime.h>
#include <cuda_bf16.h>
#include <cstdint>

#define NS    8192
#define NHALF 4096
#define D     256
#define KTOT  256          // hi-only bf16 K
#define TS    128          // output tile (M=N)
#define KC    64           // K elems per smem stage (64 bf16 = 128B rows)
#define NSTAGE (KTOT / KC) // 4
#define NTILE  64          // NS / TS
#define NBLK   (NTILE * (NTILE + 1) / 2)   // 2080 upper-triangle tiles

// ---- device-global scratch (no allocs allowed) ------------------------------
__device__ double g_acc;
__device__ float  g_colsum[D];
__device__ float  g_sq[NS];
__device__ float  g_sumsq;
__device__ float  g_C;                       // log2(e) / (16*b)
__device__ __align__(16) __nv_bfloat16 g_Y[(size_t)NS * KTOT];   // 4 MB

// ---- helpers ----------------------------------------------------------------
__device__ __forceinline__ float ex2f_fast(float x) {
    float y; asm("ex2.approx.f32 %0, %1;" : "=f"(y) : "f"(x)); return y;
}
__device__ __forceinline__ uint32_t smem_u32(const void* p) {
    uint32_t a;
    asm("{ .reg .u64 t; cvta.to.shared.u64 t, %1; cvt.u32.u64 %0, t; }" : "=r"(a) : "l"(p));
    return a;
}
__device__ __forceinline__ void cp16(uint32_t dst, const void* src) {
    asm volatile("cp.async.cg.shared.global [%0], [%1], 16;" :: "r"(dst), "l"(src));
}
#define CP_COMMIT() asm volatile("cp.async.commit_group;" ::: "memory")
#define CP_WAIT(n)  asm volatile("cp.async.wait_group %0;" :: "n"(n) : "memory")

__device__ __forceinline__ void ldm4(uint32_t* r, uint32_t a) {
    asm volatile("ldmatrix.sync.aligned.m8n8.x4.shared.b16 {%0,%1,%2,%3}, [%4];"
        : "=r"(r[0]), "=r"(r[1]), "=r"(r[2]), "=r"(r[3]) : "r"(a));
}
__device__ __forceinline__ void mma16816(float* c, const uint32_t* a, const uint32_t* b) {
    asm volatile("mma.sync.aligned.m16n8k16.row.col.f32.bf16.bf16.f32 "
        "{%0,%1,%2,%3}, {%4,%5,%6,%7}, {%8,%9}, {%0,%1,%2,%3};"
        : "+f"(c[0]), "+f"(c[1]), "+f"(c[2]), "+f"(c[3])
        : "r"(a[0]), "r"(a[1]), "r"(a[2]), "r"(a[3]), "r"(b[0]), "r"(b[1]));
}

// SW128-style XOR swizzle for tiles with 128-byte rows.
__device__ __forceinline__ uint32_t swz(uint32_t off) {
    return off ^ ((off >> 3) & 0x70);
}

__device__ __forceinline__ const float* row_ptr(const float* __restrict__ s,
                                                const float* __restrict__ t, int i) {
    return (i < NHALF) ? (s + (size_t)i * D) : (t + (size_t)(i - NHALF) * D);
}

// ---------------------------------------------------------------------------
__global__ void k_zero() {
    int t = threadIdx.x;
    if (t < D) g_colsum[t] = 0.0f;
    if (t == 0) { g_acc = 0.0; g_sumsq = 0.0f; }
}

// One warp per row: squared L2 norm; block-reduce the norms into g_sumsq.
__global__ void k_rowsq(const float* __restrict__ s, const float* __restrict__ t) {
    __shared__ float wsum[8];
    int warp = threadIdx.x >> 5, lane = threadIdx.x & 31;
    int row = blockIdx.x * 8 + warp;
    const float4* p = (const float4*)row_ptr(s, t, row);
    float4 a = p[lane];
    float4 b = p[lane + 32];
    float v = a.x * a.x + a.y * a.y + a.z * a.z + a.w * a.w
            + b.x * b.x + b.y * b.y + b.z * b.z + b.w * b.w;
    #pragma unroll
    for (int o = 16; o; o >>= 1) v += __shfl_down_sync(0xffffffffu, v, o);
    if (lane == 0) { g_sq[row] = v; wsum[warp] = v; }
    __syncthreads();
    if (threadIdx.x == 0) {
        float ss = 0.0f;
        #pragma unroll
        for (int w = 0; w < 8; ++w) ss += wsum[w];
        atomicAdd(&g_sumsq, ss);
    }
}

__global__ void k_colsum(const float* __restrict__ s, const float* __restrict__ t) {
    int d  = threadIdx.x;
    int r0 = blockIdx.x * 128;
    float acc = 0.0f;
    for (int r = r0; r < r0 + 128; ++r) acc += row_ptr(s, t, r)[d];
    atomicAdd(&g_colsum[d], acc);
}

// bandwidth: sum(l2) = 2*ns*sumsq - 2*||colsum||^2 ; b = bw/4 ;
// g_C = log2(e)/(16*b)  so  u = exp2(-l2*g_C) = exp(-l2/(16b)).
__global__ void k_bw() {
    __shared__ float red[256];
    int t = threadIdx.x;
    float c = g_colsum[t];
    red[t] = c * c; __syncthreads();
    for (int o = 128; o; o >>= 1) { if (t < o) red[t] += red[t + o]; __syncthreads(); }
    if (t == 0) {
        double suml2 = 2.0 * (double)NS * (double)g_sumsq - 2.0 * (double)red[0];
        double bw = suml2 / ((double)NS * (double)NS - (double)NS);
        double b = bw / 4.0;   // KERNEL_MUL^(KERNEL_NUM//2) = 2^2
        g_C = (float)(1.4426950408889634 / (16.0 * b));
    }
}

// bf16 hi of each fp32 value: Y[r, 0:256] = bf16(x).
__global__ void k_split(const float* __restrict__ s, const float* __restrict__ t) {
    int idx = blockIdx.x * 256 + threadIdx.x;   // one float4 (4 elems) per thread
    int row = idx >> 6;                          // 64 float4 per row
    int c4  = idx & 63;
    float4 v = ((const float4*)row_ptr(s, t, row))[c4];
    __nv_bfloat162* hi = (__nv_bfloat162*)(g_Y + (size_t)row * KTOT + c4 * 4);
    hi[0] = __nv_bfloat162(__float2bfloat16(v.x), __float2bfloat16(v.y));
    hi[1] = __nv_bfloat162(__float2bfloat16(v.z), __float2bfloat16(v.w));
}

// ---------------------------------------------------------------------------
// Warp-MMA fused Gram + multi-bandwidth Gaussian epilogue.
// 1D grid of exactly NBLK upper-triangle tiles. 128x128 tile, 8 warps *
// (64x32 warp tile). K=256 in 4 stages of 64, cp.async double-buffered,
// SW128 swizzle + ldmatrix.
#define STAGE_BYTES 32768                    // A(16KB) + B(16KB)
#define SMEM_TOTAL  (2 * STAGE_BYTES)

__global__ __launch_bounds__(256, 2) void k_mmd() {
    // linear bid -> (ib, jb), jb >= ib.  S(i) = 64i - i(i-1)/2
    int bid = blockIdx.x;
    int ib = (int)(64.5f - sqrtf(64.5f * 64.5f - 2.0f * (float)bid));
    #pragma unroll 1
    while ((64 * (ib + 1) - ((ib + 1) * ib) / 2) <= bid) ++ib;
    #pragma unroll 1
    while ((64 * ib - (ib * (ib - 1)) / 2) > bid) --ib;
    int jb = ib + (bid - (64 * ib - (ib * (ib - 1)) / 2));

    extern __shared__ char sm[];
    __shared__ float s_sqi[128], s_sqj[128], s_red[256];
    uint32_t sbase = smem_u32(sm);

    int tid  = threadIdx.x;
    int warp = tid >> 5, lane = tid & 31;
    int wm = warp >> 2, wn = warp & 3;        // warp tile: rows wm*64, cols wn*32
    int rI = ib * TS, rJ = jb * TS;

    if (tid < 128) s_sqi[tid] = g_sq[rI + tid];
    else           s_sqj[tid - 128] = g_sq[rJ + tid - 128];

    const __nv_bfloat16* YA = g_Y + (size_t)rI * KTOT;
    const __nv_bfloat16* YB = g_Y + (size_t)rJ * KTOT;

    // per-thread copy coordinates: 4 chunks of 16B for A and for B per stage
    auto issue_stage = [&](int st, int buf) {
        int k0 = st * KC;
        uint32_t base = sbase + buf * STAGE_BYTES;
        #pragma unroll
        for (int t = 0; t < 4; ++t) {
            int chunk = tid + t * 256;
            int r = chunk >> 3, c16 = chunk & 7;
            uint32_t d = swz((uint32_t)(r * 128 + c16 * 16));
            cp16(base + d,         YA + (size_t)r * KTOT + k0 + c16 * 8);
            cp16(base + 16384 + d, YB + (size_t)r * KTOT + k0 + c16 * 8);
        }
        CP_COMMIT();
    };

    float acc[4][4][4] = {};

    issue_stage(0, 0);

    for (int st = 0; st < NSTAGE; ++st) {
        if (st + 1 < NSTAGE) { issue_stage(st + 1, (st + 1) & 1); CP_WAIT(1); }
        else                 { CP_WAIT(0); }
        __syncthreads();

        uint32_t Ab = sbase + (st & 1) * STAGE_BYTES;
        uint32_t Bb = Ab + 16384;

        #pragma unroll
        for (int kk = 0; kk < KC; kk += 16) {
            int kb = (kk + ((lane >> 4) * 8)) * 2;     // byte col within 128B row
            uint32_t afr[4][4], bfr[4][2];
            #pragma unroll
            for (int i = 0; i < 4; ++i) {
                int row = wm * 64 + i * 16 + (lane & 15);
                ldm4(afr[i], Ab + swz((uint32_t)(row * 128 + kb)));
            }
            #pragma unroll
            for (int j2 = 0; j2 < 2; ++j2) {
                uint32_t q[4];
                int row = wn * 32 + j2 * 16 + (lane & 15);
                ldm4(q, Bb + swz((uint32_t)(row * 128 + kb)));
                bfr[j2 * 2 + 0][0] = q[0]; bfr[j2 * 2 + 0][1] = q[2];
                bfr[j2 * 2 + 1][0] = q[1]; bfr[j2 * 2 + 1][1] = q[3];
            }
            #pragma unroll
            for (int i = 0; i < 4; ++i)
                #pragma unroll
                for (int j = 0; j < 4; ++j)
                    mma16816(acc[i][j], afr[i], bfr[j]);
        }
        __syncthreads();
    }

    // ---- fused epilogue on C fragments ----
    float C = g_C;
    float partial = 0.0f;
    #pragma unroll
    for (int i = 0; i < 4; ++i) {
        int r_lo = wm * 64 + i * 16 + (lane >> 2);
        float sq_lo = s_sqi[r_lo], sq_hi = s_sqi[r_lo + 8];
        #pragma unroll
        for (int j = 0; j < 4; ++j) {
            int c_lo = wn * 32 + j * 8 + (lane & 3) * 2;
            float sc0 = s_sqj[c_lo], sc1 = s_sqj[c_lo + 1];
            float l2a = sq_lo + sc0 - 2.0f * acc[i][j][0];
            float l2b = sq_lo + sc1 - 2.0f * acc[i][j][1];
            float l2c = sq_hi + sc0 - 2.0f * acc[i][j][2];
            float l2d = sq_hi + sc1 - 2.0f * acc[i][j][3];
            float ua = ex2f_fast(-l2a * C), ub = ex2f_fast(-l2b * C);
            float uc = ex2f_fast(-l2c * C), ud = ex2f_fast(-l2d * C);
            float t, s4 = 0.0f;
            t = ua; s4 += t; t *= t; s4 += t; t *= t; s4 += t; t *= t; s4 += t; t *= t; s4 += t;
            t = ub; s4 += t; t *= t; s4 += t; t *= t; s4 += t; t *= t; s4 += t; t *= t; s4 += t;
            t = uc; s4 += t; t *= t; s4 += t; t *= t; s4 += t; t *= t; s4 += t; t *= t; s4 += t;
            t = ud; s4 += t; t *= t; s4 += t; t *= t; s4 += t; t *= t; s4 += t; t *= t; s4 += t;
            partial += s4;
        }
    }
    float sgn = ((ib < 32) == (jb < 32)) ? 1.0f : -1.0f;
    partial *= (ib == jb) ? sgn : 2.0f * sgn;

    s_red[tid] = partial;
    __syncthreads();
    for (int o = 128; o >= 32; o >>= 1) {
        if (tid < o) s_red[tid] += s_red[tid + o];
        __syncthreads();
    }
    if (tid < 32) {
        float v = s_red[tid];
        #pragma unroll
        for (int o = 16; o; o >>= 1) v += __shfl_down_sync(0xffffffffu, v, o);
        if (tid == 0) atomicAdd(&g_acc, (double)v);
    }
}

__global__ void k_fin(float* out) {
    out[0] = (float)(g_acc / ((double)NHALF * (double)NHALF));
}

// ---------------------------------------------------------------------------
extern "C" void kernel_launch(void* const* d_in, const int* in_sizes, int n_in,
                              void* d_out, int out_size) {
    const float* s = (const float*)d_in[0];
    const float* t = (const float*)d_in[1];
    float* out = (float*)d_out;

    cudaFuncSetAttribute(k_mmd, cudaFuncAttributeMaxDynamicSharedMemorySize, SMEM_TOTAL);

    k_zero<<<1, 256>>>();
    k_rowsq<<<1024, 256>>>(s, t);
    k_colsum<<<64, 256>>>(s, t);
    k_split<<<2048, 256>>>(s, t);
    k_bw<<<1, 256>>>();
    k_mmd<<<NBLK, 256, SMEM_TOTAL>>>();
    k_fin<<<1, 1>>>(out);
}

// round 7
// speedup vs baseline: 6.1338x; 1.0928x over previous
#include <cuda_runtime.h>
#include <cuda_bf16.h>
#include <cstdint>

#define NS    8192
#define NHALF 4096
#define D     256
#define KTOT  256          // hi-only bf16 K
#define TS    128          // output tile (M=N)
#define KC    64           // K elems per smem stage (64 bf16 = 128B rows)
#define NSTAGE (KTOT / KC) // 4
#define NTILE  64          // NS / TS
#define NBLK   (NTILE * (NTILE + 1) / 2)   // 2080 upper-triangle tiles

// ---- device-global scratch (no allocs allowed) ------------------------------
__device__ double g_acc;
__device__ float  g_colsum[D];
__device__ float  g_sq[NS];
__device__ float  g_sumsq;
__device__ float  g_C;                       // log2(e) / (16*b)
__device__ __align__(16) __nv_bfloat16 g_Y[(size_t)NS * KTOT];   // 4 MB

// ---- helpers ----------------------------------------------------------------
__device__ __forceinline__ float ex2f_fast(float x) {
    float y; asm("ex2.approx.f32 %0, %1;" : "=f"(y) : "f"(x)); return y;
}
__device__ __forceinline__ uint32_t smem_u32(const void* p) {
    uint32_t a;
    asm("{ .reg .u64 t; cvta.to.shared.u64 t, %1; cvt.u32.u64 %0, t; }" : "=r"(a) : "l"(p));
    return a;
}
__device__ __forceinline__ void cp16(uint32_t dst, const void* src) {
    asm volatile("cp.async.cg.shared.global [%0], [%1], 16;" :: "r"(dst), "l"(src));
}
#define CP_COMMIT() asm volatile("cp.async.commit_group;" ::: "memory")
#define CP_WAIT(n)  asm volatile("cp.async.wait_group %0;" :: "n"(n) : "memory")

__device__ __forceinline__ void ldm4(uint32_t* r, uint32_t a) {
    asm volatile("ldmatrix.sync.aligned.m8n8.x4.shared.b16 {%0,%1,%2,%3}, [%4];"
        : "=r"(r[0]), "=r"(r[1]), "=r"(r[2]), "=r"(r[3]) : "r"(a));
}
__device__ __forceinline__ void mma16816(float* c, const uint32_t* a, const uint32_t* b) {
    asm volatile("mma.sync.aligned.m16n8k16.row.col.f32.bf16.bf16.f32 "
        "{%0,%1,%2,%3}, {%4,%5,%6,%7}, {%8,%9}, {%0,%1,%2,%3};"
        : "+f"(c[0]), "+f"(c[1]), "+f"(c[2]), "+f"(c[3])
        : "r"(a[0]), "r"(a[1]), "r"(a[2]), "r"(a[3]), "r"(b[0]), "r"(b[1]));
}

// SW128-style XOR swizzle for tiles with 128-byte rows.
__device__ __forceinline__ uint32_t swz(uint32_t off) {
    return off ^ ((off >> 3) & 0x70);
}

__device__ __forceinline__ const float* row_ptr(const float* __restrict__ s,
                                                const float* __restrict__ t, int i) {
    return (i < NHALF) ? (s + (size_t)i * D) : (t + (size_t)(i - NHALF) * D);
}

// ---------------------------------------------------------------------------
__global__ void k_zero() {
    int t = threadIdx.x;
    if (t < D) g_colsum[t] = 0.0f;
    if (t == 0) { g_acc = 0.0; g_sumsq = 0.0f; }
}

// Fused prep: per-row L2 norm, global sum of norms, column sums, bf16 write.
// 8 rows per block (one warp each). Reads input once.
__global__ __launch_bounds__(256) void k_prep(const float* __restrict__ s,
                                              const float* __restrict__ t) {
    __shared__ float colp[8][256];
    __shared__ float wsum[8];
    int warp = threadIdx.x >> 5, lane = threadIdx.x & 31;
    int row = blockIdx.x * 8 + warp;
    const float4* p = (const float4*)row_ptr(s, t, row);
    float4 a = p[lane];          // cols 4*lane .. 4*lane+3
    float4 b = p[lane + 32];     // cols 128+4*lane ..

    // norm
    float v = a.x * a.x + a.y * a.y + a.z * a.z + a.w * a.w
            + b.x * b.x + b.y * b.y + b.z * b.z + b.w * b.w;
    #pragma unroll
    for (int o = 16; o; o >>= 1) v += __shfl_down_sync(0xffffffffu, v, o);
    if (lane == 0) { g_sq[row] = v; wsum[warp] = v; }

    // bf16 hi write
    __nv_bfloat162* h0 = (__nv_bfloat162*)(g_Y + (size_t)row * KTOT + lane * 4);
    h0[0] = __nv_bfloat162(__float2bfloat16(a.x), __float2bfloat16(a.y));
    h0[1] = __nv_bfloat162(__float2bfloat16(a.z), __float2bfloat16(a.w));
    __nv_bfloat162* h1 = (__nv_bfloat162*)(g_Y + (size_t)row * KTOT + 128 + lane * 4);
    h1[0] = __nv_bfloat162(__float2bfloat16(b.x), __float2bfloat16(b.y));
    h1[1] = __nv_bfloat162(__float2bfloat16(b.z), __float2bfloat16(b.w));

    // column partials staged in smem
    ((float4*)colp[warp])[lane]      = a;
    ((float4*)colp[warp])[lane + 32] = b;
    __syncthreads();

    int tidx = threadIdx.x;            // 0..255 = column index
    float cs = 0.0f;
    #pragma unroll
    for (int r = 0; r < 8; ++r) cs += colp[r][tidx];
    atomicAdd(&g_colsum[tidx], cs);
    if (tidx == 0) {
        float ss = 0.0f;
        #pragma unroll
        for (int w = 0; w < 8; ++w) ss += wsum[w];
        atomicAdd(&g_sumsq, ss);
    }
}

// bandwidth: sum(l2) = 2*ns*sumsq - 2*||colsum||^2 ; b = bw/4 ;
// g_C = log2(e)/(16*b)  so  u = exp2(-l2*g_C) = exp(-l2/(16b)).
__global__ void k_bw() {
    __shared__ float red[256];
    int t = threadIdx.x;
    float c = g_colsum[t];
    red[t] = c * c; __syncthreads();
    for (int o = 128; o; o >>= 1) { if (t < o) red[t] += red[t + o]; __syncthreads(); }
    if (t == 0) {
        double suml2 = 2.0 * (double)NS * (double)g_sumsq - 2.0 * (double)red[0];
        double bw = suml2 / ((double)NS * (double)NS - (double)NS);
        double b = bw / 4.0;   // KERNEL_MUL^(KERNEL_NUM//2) = 2^2
        g_C = (float)(1.4426950408889634 / (16.0 * b));
    }
}

// ---------------------------------------------------------------------------
// Warp-MMA fused Gram + multi-bandwidth Gaussian epilogue.
// 4 warps / CTA (128 thr), 64x64 warp tiles over a 128x128 CTA tile.
// K=256 in 4 stages, cp.async double-buffered smem, register double-buffered
// fragments (prefetch k-step kk+1 LDSM before kk MMAs).
#define STAGE_BYTES 32768                    // A(16KB) + B(16KB)
#define SMEM_TOTAL  (2 * STAGE_BYTES)

__device__ __forceinline__ void load_frags(uint32_t Ab, uint32_t Bb, int kk,
                                           int lane, int wm, int wn,
                                           uint32_t afr[4][4], uint32_t bfr[8][2]) {
    int kb = (kk * 16 + ((lane >> 4) * 8)) * 2;   // byte col within 128B row
    #pragma unroll
    for (int i = 0; i < 4; ++i) {
        int row = wm * 64 + i * 16 + (lane & 15);
        ldm4(afr[i], Ab + swz((uint32_t)(row * 128 + kb)));
    }
    #pragma unroll
    for (int j2 = 0; j2 < 4; ++j2) {
        uint32_t q[4];
        int row = wn * 64 + j2 * 16 + (lane & 15);
        ldm4(q, Bb + swz((uint32_t)(row * 128 + kb)));
        bfr[j2 * 2 + 0][0] = q[0]; bfr[j2 * 2 + 0][1] = q[2];
        bfr[j2 * 2 + 1][0] = q[1]; bfr[j2 * 2 + 1][1] = q[3];
    }
}

__global__ __launch_bounds__(128, 2) void k_mmd() {
    // linear bid -> (ib, jb), jb >= ib.
    int bid = blockIdx.x;
    int ib = (int)(64.5f - sqrtf(64.5f * 64.5f - 2.0f * (float)bid));
    #pragma unroll 1
    while ((64 * (ib + 1) - ((ib + 1) * ib) / 2) <= bid) ++ib;
    #pragma unroll 1
    while ((64 * ib - (ib * (ib - 1)) / 2) > bid) --ib;
    int jb = ib + (bid - (64 * ib - (ib * (ib - 1)) / 2));

    extern __shared__ char sm[];
    __shared__ float s_sqi[128], s_sqj[128], s_red[128];
    uint32_t sbase = smem_u32(sm);

    int tid  = threadIdx.x;
    int warp = tid >> 5, lane = tid & 31;
    int wm = warp >> 1, wn = warp & 1;        // warp tile: rows wm*64, cols wn*64
    int rI = ib * TS, rJ = jb * TS;

    s_sqi[tid] = g_sq[rI + tid];
    s_sqj[tid] = g_sq[rJ + tid];

    const __nv_bfloat16* YA = g_Y + (size_t)rI * KTOT;
    const __nv_bfloat16* YB = g_Y + (size_t)rJ * KTOT;

    auto issue_stage = [&](int st, int buf) {
        int k0 = st * KC;
        uint32_t base = sbase + buf * STAGE_BYTES;
        #pragma unroll
        for (int t = 0; t < 8; ++t) {
            int chunk = tid + t * 128;           // 0..1023
            int r = chunk >> 3, c16 = chunk & 7;
            uint32_t d = swz((uint32_t)(r * 128 + c16 * 16));
            cp16(base + d,         YA + (size_t)r * KTOT + k0 + c16 * 8);
            cp16(base + 16384 + d, YB + (size_t)r * KTOT + k0 + c16 * 8);
        }
        CP_COMMIT();
    };

    float acc[4][8][4] = {};
    uint32_t afr[2][4][4], bfr[2][8][2];

    issue_stage(0, 0);

    for (int st = 0; st < NSTAGE; ++st) {
        if (st + 1 < NSTAGE) { issue_stage(st + 1, (st + 1) & 1); CP_WAIT(1); }
        else                 { CP_WAIT(0); }
        __syncthreads();

        uint32_t Ab = sbase + (st & 1) * STAGE_BYTES;
        uint32_t Bb = Ab + 16384;

        load_frags(Ab, Bb, 0, lane, wm, wn, afr[0], bfr[0]);
        #pragma unroll
        for (int kk = 0; kk < 4; ++kk) {
            int cur = kk & 1;
            if (kk < 3)
                load_frags(Ab, Bb, kk + 1, lane, wm, wn, afr[cur ^ 1], bfr[cur ^ 1]);
            #pragma unroll
            for (int i = 0; i < 4; ++i)
                #pragma unroll
                for (int j = 0; j < 8; ++j)
                    mma16816(acc[i][j], afr[cur][i], bfr[cur][j]);
        }
        __syncthreads();
    }

    // ---- fused epilogue on C fragments ----
    float C = g_C;
    float partial = 0.0f;
    #pragma unroll
    for (int i = 0; i < 4; ++i) {
        int r_lo = wm * 64 + i * 16 + (lane >> 2);
        float sq_lo = s_sqi[r_lo], sq_hi = s_sqi[r_lo + 8];
        #pragma unroll
        for (int j = 0; j < 8; ++j) {
            int c_lo = wn * 64 + j * 8 + (lane & 3) * 2;
            float sc0 = s_sqj[c_lo], sc1 = s_sqj[c_lo + 1];
            float l2a = sq_lo + sc0 - 2.0f * acc[i][j][0];
            float l2b = sq_lo + sc1 - 2.0f * acc[i][j][1];
            float l2c = sq_hi + sc0 - 2.0f * acc[i][j][2];
            float l2d = sq_hi + sc1 - 2.0f * acc[i][j][3];
            float ua = ex2f_fast(-l2a * C), ub = ex2f_fast(-l2b * C);
            float uc = ex2f_fast(-l2c * C), ud = ex2f_fast(-l2d * C);
            float t, s4 = 0.0f;
            t = ua; s4 += t; t *= t; s4 += t; t *= t; s4 += t; t *= t; s4 += t; t *= t; s4 += t;
            t = ub; s4 += t; t *= t; s4 += t; t *= t; s4 += t; t *= t; s4 += t; t *= t; s4 += t;
            t = uc; s4 += t; t *= t; s4 += t; t *= t; s4 += t; t *= t; s4 += t; t *= t; s4 += t;
            t = ud; s4 += t; t *= t; s4 += t; t *= t; s4 += t; t *= t; s4 += t; t *= t; s4 += t;
            partial += s4;
        }
    }
    float sgn = ((ib < 32) == (jb < 32)) ? 1.0f : -1.0f;
    partial *= (ib == jb) ? sgn : 2.0f * sgn;

    s_red[tid] = partial;
    __syncthreads();
    if (tid < 64) s_red[tid] += s_red[tid + 64];
    __syncthreads();
    if (tid < 32) {
        float v = s_red[tid] + s_red[tid + 32];
        #pragma unroll
        for (int o = 16; o; o >>= 1) v += __shfl_down_sync(0xffffffffu, v, o);
        if (tid == 0) atomicAdd(&g_acc, (double)v);
    }
}

__global__ void k_fin(float* out) {
    out[0] = (float)(g_acc / ((double)NHALF * (double)NHALF));
}

// ---------------------------------------------------------------------------
extern "C" void kernel_launch(void* const* d_in, const int* in_sizes, int n_in,
                              void* d_out, int out_size) {
    const float* s = (const float*)d_in[0];
    const float* t = (const float*)d_in[1];
    float* out = (float*)d_out;

    cudaFuncSetAttribute(k_mmd, cudaFuncAttributeMaxDynamicSharedMemorySize, SMEM_TOTAL);

    k_zero<<<1, 256>>>();
    k_prep<<<1024, 256>>>(s, t);
    k_bw<<<1, 256>>>();
    k_mmd<<<NBLK, 128, SMEM_TOTAL>>>();
    k_fin<<<1, 1>>>(out);
}

// round 8
// speedup vs baseline: 6.2630x; 1.0211x over previous
#include <cuda_runtime.h>
#include <cuda_bf16.h>
#include <cstdint>

#define NS    8192
#define NHALF 4096
#define D     256
#define KTOT  256          // hi-only bf16 K
#define TS    128          // output tile (M=N)
#define KC    64           // K elems per smem stage (64 bf16 = 128B rows)
#define NSTAGE (KTOT / KC) // 4
#define NTILE  64          // NS / TS
#define NBLK   (NTILE * (NTILE + 1) / 2)   // 2080 upper-triangle tiles
#define PREPB  256         // k_prep blocks (32 rows each)

// ---- device-global scratch (no allocs allowed) ------------------------------
__device__ double g_acc;
__device__ float  g_colpart[PREPB * D];      // per-block column-sum partials
__device__ float  g_sqpart[PREPB];           // per-block sum-of-norms partials
__device__ float  g_sq[NS];
__device__ float  g_C;                       // log2(e) / (16*b)
__device__ __align__(16) __nv_bfloat16 g_Y[(size_t)NS * KTOT];   // 4 MB

// ---- helpers ----------------------------------------------------------------
__device__ __forceinline__ float ex2f_fast(float x) {
    float y; asm("ex2.approx.f32 %0, %1;" : "=f"(y) : "f"(x)); return y;
}
__device__ __forceinline__ uint32_t smem_u32(const void* p) {
    uint32_t a;
    asm("{ .reg .u64 t; cvta.to.shared.u64 t, %1; cvt.u32.u64 %0, t; }" : "=r"(a) : "l"(p));
    return a;
}
__device__ __forceinline__ void cp16(uint32_t dst, const void* src) {
    asm volatile("cp.async.cg.shared.global [%0], [%1], 16;" :: "r"(dst), "l"(src));
}
#define CP_COMMIT() asm volatile("cp.async.commit_group;" ::: "memory")
#define CP_WAIT(n)  asm volatile("cp.async.wait_group %0;" :: "n"(n) : "memory")

__device__ __forceinline__ void ldm4(uint32_t* r, uint32_t a) {
    asm volatile("ldmatrix.sync.aligned.m8n8.x4.shared.b16 {%0,%1,%2,%3}, [%4];"
        : "=r"(r[0]), "=r"(r[1]), "=r"(r[2]), "=r"(r[3]) : "r"(a));
}
__device__ __forceinline__ void mma16816(float* c, const uint32_t* a, const uint32_t* b) {
    asm volatile("mma.sync.aligned.m16n8k16.row.col.f32.bf16.bf16.f32 "
        "{%0,%1,%2,%3}, {%4,%5,%6,%7}, {%8,%9}, {%0,%1,%2,%3};"
        : "+f"(c[0]), "+f"(c[1]), "+f"(c[2]), "+f"(c[3])
        : "r"(a[0]), "r"(a[1]), "r"(a[2]), "r"(a[3]), "r"(b[0]), "r"(b[1]));
}

// SW128-style XOR swizzle for tiles with 128-byte rows (used in cp path only).
__device__ __forceinline__ uint32_t swz(uint32_t off) {
    return off ^ ((off >> 3) & 0x70);
}

__device__ __forceinline__ const float* row_ptr(const float* __restrict__ s,
                                                const float* __restrict__ t, int i) {
    return (i < NHALF) ? (s + (size_t)i * D) : (t + (size_t)(i - NHALF) * D);
}

// ---------------------------------------------------------------------------
// Fused prep: per-row L2 norms, per-block norm-sum and column-sum partials,
// bf16 write. 32 rows per block (4 per warp). Also zero-inits g_acc (benign
// same-value multi-write; ordered before k_mmd atomics by kernel ordering).
__global__ __launch_bounds__(256) void k_prep(const float* __restrict__ s,
                                              const float* __restrict__ t) {
    __shared__ float colp[8][256];
    __shared__ float wsum[8];
    int warp = threadIdx.x >> 5, lane = threadIdx.x & 31;

    float4 ca = make_float4(0.f, 0.f, 0.f, 0.f);
    float4 cb = make_float4(0.f, 0.f, 0.f, 0.f);
    float normsum = 0.0f;

    #pragma unroll
    for (int r = 0; r < 4; ++r) {
        int row = blockIdx.x * 32 + warp * 4 + r;
        const float4* p = (const float4*)row_ptr(s, t, row);
        float4 a = p[lane];          // cols 4*lane .. 4*lane+3
        float4 b = p[lane + 32];     // cols 128+4*lane ..

        float v = a.x * a.x + a.y * a.y + a.z * a.z + a.w * a.w
                + b.x * b.x + b.y * b.y + b.z * b.z + b.w * b.w;
        #pragma unroll
        for (int o = 16; o; o >>= 1) v += __shfl_down_sync(0xffffffffu, v, o);
        if (lane == 0) { g_sq[row] = v; normsum += v; }

        __nv_bfloat162* h0 = (__nv_bfloat162*)(g_Y + (size_t)row * KTOT + lane * 4);
        h0[0] = __nv_bfloat162(__float2bfloat16(a.x), __float2bfloat16(a.y));
        h0[1] = __nv_bfloat162(__float2bfloat16(a.z), __float2bfloat16(a.w));
        __nv_bfloat162* h1 = (__nv_bfloat162*)(g_Y + (size_t)row * KTOT + 128 + lane * 4);
        h1[0] = __nv_bfloat162(__float2bfloat16(b.x), __float2bfloat16(b.y));
        h1[1] = __nv_bfloat162(__float2bfloat16(b.z), __float2bfloat16(b.w));

        ca.x += a.x; ca.y += a.y; ca.z += a.z; ca.w += a.w;
        cb.x += b.x; cb.y += b.y; cb.z += b.z; cb.w += b.w;
    }

    ((float4*)colp[warp])[lane]      = ca;
    ((float4*)colp[warp])[lane + 32] = cb;
    if (lane == 0) wsum[warp] = normsum;
    __syncthreads();

    int tid = threadIdx.x;           // 0..255 = column index
    float cs = 0.0f;
    #pragma unroll
    for (int w = 0; w < 8; ++w) cs += colp[w][tid];
    g_colpart[blockIdx.x * D + tid] = cs;
    if (tid == 0) {
        float ss = 0.0f;
        #pragma unroll
        for (int w = 0; w < 8; ++w) ss += wsum[w];
        g_sqpart[blockIdx.x] = ss;
        g_acc = 0.0;
    }
}

// bandwidth: sum(l2) = 2*ns*sumsq - 2*||colsum||^2 ; b = bw/4 ;
// g_C = log2(e)/(16*b)  so  u = exp2(-l2*g_C) = exp(-l2/(16b)).
__global__ void k_bw() {
    __shared__ float red[256];
    int t = threadIdx.x;
    float cs = 0.0f;
    #pragma unroll 8
    for (int b = 0; b < PREPB; ++b) cs += g_colpart[b * D + t];
    red[t] = cs * cs;
    __syncthreads();
    for (int o = 128; o; o >>= 1) { if (t < o) red[t] += red[t + o]; __syncthreads(); }
    float csq = red[0];
    __syncthreads();
    red[t] = g_sqpart[t];            // PREPB == 256
    __syncthreads();
    for (int o = 128; o; o >>= 1) { if (t < o) red[t] += red[t + o]; __syncthreads(); }
    if (t == 0) {
        double suml2 = 2.0 * (double)NS * (double)red[0] - 2.0 * (double)csq;
        double bw = suml2 / ((double)NS * (double)NS - (double)NS);
        double b = bw / 4.0;   // KERNEL_MUL^(KERNEL_NUM//2) = 2^2
        g_C = (float)(1.4426950408889634 / (16.0 * b));
    }
}

// ---------------------------------------------------------------------------
// Warp-MMA fused Gram + multi-bandwidth Gaussian epilogue.
// 4 warps / CTA (128 thr), 64x64 warp tiles over a 128x128 CTA tile.
// K=256 in 4 stages, 3-stage cp.async smem pipeline (one sync per stage),
// register double-buffered fragments, hoisted LDSM addressing.
#define STAGE_BYTES 32768                    // A(16KB) + B(16KB)
#define SMEM_TOTAL  (3 * STAGE_BYTES)        // 96KB, 2 CTAs/SM

__device__ __forceinline__ void load_frags(uint32_t Ab, uint32_t Bb, uint32_t koff,
                                           const uint32_t* ra, const uint32_t* rb,
                                           uint32_t afr[4][4], uint32_t bfr[8][2]) {
    #pragma unroll
    for (int i = 0; i < 4; ++i)
        ldm4(afr[i], Ab + ra[i] + koff);
    #pragma unroll
    for (int j2 = 0; j2 < 4; ++j2) {
        uint32_t q[4];
        ldm4(q, Bb + rb[j2] + koff);
        bfr[j2 * 2 + 0][0] = q[0]; bfr[j2 * 2 + 0][1] = q[2];
        bfr[j2 * 2 + 1][0] = q[1]; bfr[j2 * 2 + 1][1] = q[3];
    }
}

__global__ __launch_bounds__(128, 2) void k_mmd() {
    // linear bid -> (ib, jb), jb >= ib.
    int bid = blockIdx.x;
    int ib = (int)(64.5f - sqrtf(64.5f * 64.5f - 2.0f * (float)bid));
    #pragma unroll 1
    while ((64 * (ib + 1) - ((ib + 1) * ib) / 2) <= bid) ++ib;
    #pragma unroll 1
    while ((64 * ib - (ib * (ib - 1)) / 2) > bid) --ib;
    int jb = ib + (bid - (64 * ib - (ib * (ib - 1)) / 2));

    extern __shared__ char sm[];
    __shared__ float s_nCi[128], s_nCj[128], s_red[128];
    uint32_t sbase = smem_u32(sm);

    int tid  = threadIdx.x;
    int warp = tid >> 5, lane = tid & 31;
    int wm = warp >> 1, wn = warp & 1;        // warp tile: rows wm*64, cols wn*64
    int rI = ib * TS, rJ = jb * TS;

    float C = g_C;
    s_nCi[tid] = -C * g_sq[rI + tid];
    s_nCj[tid] = -C * g_sq[rJ + tid];

    const __nv_bfloat16* YA = g_Y + (size_t)rI * KTOT;
    const __nv_bfloat16* YB = g_Y + (size_t)rJ * KTOT;

    // hoisted LDSM addressing: swz(row*128+kb) == row*128 + (kb ^ ((lane&7)<<4))
    int lane15 = lane & 15;
    uint32_t xr  = (uint32_t)((lane & 7) << 4);
    uint32_t kb0 = (uint32_t)((lane >> 4) * 16);
    uint32_t ra[4], rb[4];
    #pragma unroll
    for (int i = 0; i < 4; ++i) {
        ra[i] = (uint32_t)((wm * 64 + i * 16 + lane15) * 128);
        rb[i] = (uint32_t)((wn * 64 + i * 16 + lane15) * 128);
    }

    auto issue_stage = [&](int st, int buf) {
        int k0 = st * KC;
        uint32_t base = sbase + buf * STAGE_BYTES;
        #pragma unroll
        for (int t = 0; t < 8; ++t) {
            int chunk = tid + t * 128;           // 0..1023
            int r = chunk >> 3, c16 = chunk & 7;
            uint32_t d = swz((uint32_t)(r * 128 + c16 * 16));
            cp16(base + d,         YA + (size_t)r * KTOT + k0 + c16 * 8);
            cp16(base + 16384 + d, YB + (size_t)r * KTOT + k0 + c16 * 8);
        }
        CP_COMMIT();
    };

    float acc[4][8][4] = {};
    uint32_t afr[2][4][4], bfr[2][8][2];

    issue_stage(0, 0);
    issue_stage(1, 1);

    #pragma unroll
    for (int st = 0; st < NSTAGE; ++st) {
        if (st < NSTAGE - 1) CP_WAIT(1);
        else                 CP_WAIT(0);
        __syncthreads();      // all warps done with stage st-1's buffer
        if (st + 2 < NSTAGE) issue_stage(st + 2, (st + 2) % 3);

        uint32_t Ab = sbase + (st % 3) * STAGE_BYTES;
        uint32_t Bb = Ab + 16384;

        load_frags(Ab, Bb, kb0 ^ xr, ra, rb, afr[0], bfr[0]);
        #pragma unroll
        for (int kk = 0; kk < 4; ++kk) {
            int cur = kk & 1;
            if (kk < 3) {
                uint32_t koff = ((uint32_t)((kk + 1) << 5) | kb0) ^ xr;
                load_frags(Ab, Bb, koff, ra, rb, afr[cur ^ 1], bfr[cur ^ 1]);
            }
            #pragma unroll
            for (int i = 0; i < 4; ++i)
                #pragma unroll
                for (int j = 0; j < 8; ++j)
                    mma16816(acc[i][j], afr[cur][i], bfr[cur][j]);
        }
    }

    // ---- fused epilogue: arg = 2C*g - C*si - C*sj = fma(twoC, g, nCi+nCj) ----
    float twoC = 2.0f * C;
    float partial = 0.0f;
    #pragma unroll
    for (int i = 0; i < 4; ++i) {
        int r_lo = wm * 64 + i * 16 + (lane >> 2);
        float ni_lo = s_nCi[r_lo], ni_hi = s_nCi[r_lo + 8];
        #pragma unroll
        for (int j = 0; j < 8; ++j) {
            int c_lo = wn * 64 + j * 8 + (lane & 3) * 2;
            float nj0 = s_nCj[c_lo], nj1 = s_nCj[c_lo + 1];
            float ua = ex2f_fast(fmaf(twoC, acc[i][j][0], ni_lo + nj0));
            float ub = ex2f_fast(fmaf(twoC, acc[i][j][1], ni_lo + nj1));
            float uc = ex2f_fast(fmaf(twoC, acc[i][j][2], ni_hi + nj0));
            float ud = ex2f_fast(fmaf(twoC, acc[i][j][3], ni_hi + nj1));
            // u + u^2 + u^4 + u^8 + u^16 via 3 mul + 1 fma + 4 add
            #pragma unroll
            for (int e = 0; e < 4; ++e) {
                float u = (e == 0) ? ua : (e == 1) ? ub : (e == 2) ? uc : ud;
                float u2 = u * u;
                float u4 = u2 * u2;
                float u8 = u4 * u4;
                float hi = fmaf(u8, u8, u8);        // u16 + u8
                partial += (u + u2) + (u4 + hi);
            }
        }
    }
    float sgn = ((ib < 32) == (jb < 32)) ? 1.0f : -1.0f;
    partial *= (ib == jb) ? sgn : 2.0f * sgn;

    s_red[tid] = partial;
    __syncthreads();
    if (tid < 64) s_red[tid] += s_red[tid + 64];
    __syncthreads();
    if (tid < 32) {
        float v = s_red[tid] + s_red[tid + 32];
        #pragma unroll
        for (int o = 16; o; o >>= 1) v += __shfl_down_sync(0xffffffffu, v, o);
        if (tid == 0) atomicAdd(&g_acc, (double)v);
    }
}

__global__ void k_fin(float* out) {
    out[0] = (float)(g_acc / ((double)NHALF * (double)NHALF));
}

// ---------------------------------------------------------------------------
extern "C" void kernel_launch(void* const* d_in, const int* in_sizes, int n_in,
                              void* d_out, int out_size) {
    const float* s = (const float*)d_in[0];
    const float* t = (const float*)d_in[1];
    float* out = (float*)d_out;

    cudaFuncSetAttribute(k_mmd, cudaFuncAttributeMaxDynamicSharedMemorySize, SMEM_TOTAL);

    k_prep<<<PREPB, 256>>>(s, t);
    k_bw<<<1, 256>>>();
    k_mmd<<<NBLK, 128, SMEM_TOTAL>>>();
    k_fin<<<1, 1>>>(out);
}